// round 3
// baseline (speedup 1.0000x reference)
#include <cuda_runtime.h>
#include <cuda_bf16.h>
#include <cstdint>

// ---------------------------------------------------------------------------
// GNN_85366769975686:
//   layer(feat, W, b): m = feat@W + b ; agg = segment_sum(m[src], dst)
//                      return concat([agg, m], -1)
//   out = layer(layer(features, W1, b1), W2, b2)
// N = 50000 nodes, E = 800000 edges, D = 128, output [N, 256] fp32.
// ---------------------------------------------------------------------------

#define N_NODES   50000
#define N_PAD     50048          // 391 * 128
#define D_OUT     128
#define LDC       256            // row stride of concat buffers

// Scratch: layer-1 concat buffer [N_PAD, 256]  (~51.2 MB)
__device__ float g_feat1[(size_t)N_PAD * LDC];

// ---------------------------------------------------------------------------
// SGEMM: C_m[row, col] = sum_k A[row,k] * W[k,col] + bias[col]
//   A: [M, K] row-major with leading dim lda
//   W: [K, 128] row-major
//   C: row stride 256; writes result to cols [128,256), zeros cols [0,128)
// Block: 256 threads, tile 128 rows x 128 cols, 8x8 per thread, K-tile 16.
// ---------------------------------------------------------------------------
__global__ __launch_bounds__(256)
void gemm_bias_zero(const float* __restrict__ A, int lda,
                    const float* __restrict__ W,
                    const float* __restrict__ bias,
                    float* __restrict__ C,
                    int M, int K)
{
    __shared__ float As[16][132];   // [k][row], padded (132*4 % 16 == 0)
    __shared__ float Bs[16][128];   // [k][col]

    const int t  = threadIdx.x;
    const int tx = t & 15;          // col group
    const int ty = t >> 4;          // row group
    const int row0 = blockIdx.x * 128;

    float acc[8][8];
#pragma unroll
    for (int i = 0; i < 8; i++)
#pragma unroll
        for (int j = 0; j < 8; j++) acc[i][j] = 0.0f;

    for (int k0 = 0; k0 < K; k0 += 16) {
        // --- load A tile: 128 rows x 16 k = 512 float4, 2 per thread ---
#pragma unroll
        for (int l = 0; l < 2; l++) {
            int idx = t + l * 256;
            int row = idx >> 2;
            int f4  = idx & 3;
            int gr  = row0 + row;
            float4 v = make_float4(0.f, 0.f, 0.f, 0.f);
            if (gr < M)
                v = *reinterpret_cast<const float4*>(A + (size_t)gr * lda + k0 + f4 * 4);
            As[f4 * 4 + 0][row] = v.x;
            As[f4 * 4 + 1][row] = v.y;
            As[f4 * 4 + 2][row] = v.z;
            As[f4 * 4 + 3][row] = v.w;
        }
        // --- load B tile: 16 k x 128 cols = 512 float4, 2 per thread ---
#pragma unroll
        for (int l = 0; l < 2; l++) {
            int idx = t + l * 256;
            int k   = idx >> 5;
            int c4  = idx & 31;
            *reinterpret_cast<float4*>(&Bs[k][c4 * 4]) =
                *reinterpret_cast<const float4*>(W + (size_t)(k0 + k) * 128 + c4 * 4);
        }
        __syncthreads();

#pragma unroll
        for (int kk = 0; kk < 16; kk++) {
            float a[8], b[8];
            *reinterpret_cast<float4*>(a)     = *reinterpret_cast<const float4*>(&As[kk][ty * 8]);
            *reinterpret_cast<float4*>(a + 4) = *reinterpret_cast<const float4*>(&As[kk][ty * 8 + 4]);
            *reinterpret_cast<float4*>(b)     = *reinterpret_cast<const float4*>(&Bs[kk][tx * 8]);
            *reinterpret_cast<float4*>(b + 4) = *reinterpret_cast<const float4*>(&Bs[kk][tx * 8 + 4]);
#pragma unroll
            for (int i = 0; i < 8; i++)
#pragma unroll
                for (int j = 0; j < 8; j++)
                    acc[i][j] = fmaf(a[i], b[j], acc[i][j]);
        }
        __syncthreads();
    }

    // --- epilogue: +bias, store to cols 128.., zero cols 0.. ---
    float bl[8];
    *reinterpret_cast<float4*>(bl)     = *reinterpret_cast<const float4*>(bias + tx * 8);
    *reinterpret_cast<float4*>(bl + 4) = *reinterpret_cast<const float4*>(bias + tx * 8 + 4);

    const float4 zero4 = make_float4(0.f, 0.f, 0.f, 0.f);
#pragma unroll
    for (int i = 0; i < 8; i++) {
        int gr = row0 + ty * 8 + i;
        if (gr >= M) continue;
        float* crow = C + (size_t)gr * LDC;
        float4 v0, v1;
        v0.x = acc[i][0] + bl[0]; v0.y = acc[i][1] + bl[1];
        v0.z = acc[i][2] + bl[2]; v0.w = acc[i][3] + bl[3];
        v1.x = acc[i][4] + bl[4]; v1.y = acc[i][5] + bl[5];
        v1.z = acc[i][6] + bl[6]; v1.w = acc[i][7] + bl[7];
        *reinterpret_cast<float4*>(crow + 128 + tx * 8)     = v0;
        *reinterpret_cast<float4*>(crow + 128 + tx * 8 + 4) = v1;
        *reinterpret_cast<float4*>(crow + tx * 8)           = zero4;
        *reinterpret_cast<float4*>(crow + tx * 8 + 4)       = zero4;
    }
}

// ---------------------------------------------------------------------------
// Scatter-add: one warp per edge. Each lane owns one float4 (32*16B = 512B).
//   msg points at the m-half (already offset by +128 floats), row stride 256.
//   agg points at the agg-half (col 0), row stride 256.
// Uses sm_90+ vector atomicAdd(float4*) -> RED.ADD.F32x4.
// ---------------------------------------------------------------------------
__global__ __launch_bounds__(256)
void scatter_add_kernel(const float* __restrict__ msg,
                        float* __restrict__ agg,
                        const int* __restrict__ src,
                        const int* __restrict__ dst,
                        int E)
{
    int gw   = (blockIdx.x * blockDim.x + threadIdx.x) >> 5;
    int lane = threadIdx.x & 31;
    if (gw >= E) return;

    int s = __ldg(src + gw);
    int d = __ldg(dst + gw);

    const float4* mp = reinterpret_cast<const float4*>(msg) + (size_t)s * (LDC / 4) + lane;
    float4 v = __ldg(mp);

    float4* ap = reinterpret_cast<float4*>(agg) + (size_t)d * (LDC / 4) + lane;
    atomicAdd(ap, v);
}

// ---------------------------------------------------------------------------
// Launch
// ---------------------------------------------------------------------------
extern "C" void kernel_launch(void* const* d_in, const int* in_sizes, int n_in,
                              void* d_out, int out_size)
{
    const float* features = (const float*)d_in[0];
    const int*   src      = (const int*)  d_in[1];
    const int*   dst      = (const int*)  d_in[2];
    const float* W1       = (const float*)d_in[3];
    const float* b1       = (const float*)d_in[4];
    const float* W2       = (const float*)d_in[5];
    const float* b2       = (const float*)d_in[6];
    float*       out      = (float*)d_out;

    const int M = in_sizes[0] / 128;   // 50000 nodes
    const int E = in_sizes[1];         // 800000 edges

    float* feat1 = nullptr;
    cudaGetSymbolAddress((void**)&feat1, g_feat1);

    const int gemm_blocks    = (M + 127) / 128;       // 391
    const int scatter_blocks = (E + 7) / 8;           // 8 warps/block, 1 edge/warp

    // Layer 1: m1 = features@W1+b1 -> feat1[:,128:256]; feat1[:,0:128] = 0
    gemm_bias_zero<<<gemm_blocks, 256>>>(features, 128, W1, b1, feat1, M, 128);
    // agg1 += m1[src] at dst
    scatter_add_kernel<<<scatter_blocks, 256>>>(feat1 + 128, feat1, src, dst, E);

    // Layer 2: m2 = feat1@W2+b2 -> out[:,128:256]; out[:,0:128] = 0
    gemm_bias_zero<<<gemm_blocks, 256>>>(feat1, 256, W2, b2, out, M, 256);
    // agg2 += m2[src] at dst
    scatter_add_kernel<<<scatter_blocks, 256>>>(out + 128, out, src, dst, E);
}

// round 4
// speedup vs baseline: 1.0916x; 1.0916x over previous
#include <cuda_runtime.h>
#include <cuda_bf16.h>
#include <cstdint>

// ---------------------------------------------------------------------------
// GNN_85366769975686  (R3: CSR-gather aggregation, no float atomics)
//   layer(feat, W, b): m = feat@W + b ; agg = segment_sum(m[src], dst)
//                      return concat([agg, m], -1)
// N = 50000 nodes, E = 800000 edges, D = 128, output [N, 256] fp32.
// ---------------------------------------------------------------------------

#define N_MAX     50048
#define E_MAX     800000
#define LDC       256            // row stride (floats) of concat buffers

// Scratch (static — no allocations allowed)
__device__ float g_feat1[(size_t)N_MAX * LDC];      // layer-1 concat buffer
__device__ int   g_cnt[N_MAX + 1];                  // per-dst degree
__device__ int   g_row_start[N_MAX + 1];            // CSR row offsets
__device__ int   g_cursor[N_MAX + 1];               // fill cursors
__device__ int   g_edge_src[E_MAX];                 // src ids grouped by dst

// ---------------------------------------------------------------------------
// CSR build step 1: histogram of dst
// ---------------------------------------------------------------------------
__global__ void hist_kernel(const int* __restrict__ dst, int* __restrict__ cnt, int E)
{
    int e = blockIdx.x * blockDim.x + threadIdx.x;
    if (e < E) atomicAdd(&cnt[__ldg(dst + e)], 1);
}

// ---------------------------------------------------------------------------
// CSR build step 2: single-block exclusive scan over n counts.
// 1024 threads, each owns a contiguous chunk; Hillis-Steele over chunk sums.
// Writes row_start[0..n] and cursor[0..n-1].
// ---------------------------------------------------------------------------
__global__ __launch_bounds__(1024)
void scan_kernel(const int* __restrict__ cnt,
                 int* __restrict__ row_start,
                 int* __restrict__ cursor, int n)
{
    __shared__ int sums[1024];
    const int t = threadIdx.x;
    const int chunk = (n + 1023) / 1024;
    const int lo = t * chunk;
    const int hi = min(lo + chunk, n);

    int s = 0;
    for (int i = lo; i < hi; i++) s += cnt[i];
    sums[t] = s;
    __syncthreads();

#pragma unroll
    for (int off = 1; off < 1024; off <<= 1) {
        int u = (t >= off) ? sums[t - off] : 0;
        __syncthreads();
        sums[t] += u;
        __syncthreads();
    }

    int run = sums[t] - s;          // exclusive prefix of this chunk
    for (int i = lo; i < hi; i++) {
        row_start[i] = run;
        cursor[i]    = run;
        run += cnt[i];
    }
    if (t == 1023) row_start[n] = sums[1023];
}

// ---------------------------------------------------------------------------
// CSR build step 3: scatter edge src ids into dst buckets
// ---------------------------------------------------------------------------
__global__ void fill_kernel(const int* __restrict__ src, const int* __restrict__ dst,
                            int* __restrict__ cursor, int* __restrict__ edge_src, int E)
{
    int e = blockIdx.x * blockDim.x + threadIdx.x;
    if (e < E) {
        int p = atomicAdd(&cursor[__ldg(dst + e)], 1);
        edge_src[p] = __ldg(src + e);
    }
}

// ---------------------------------------------------------------------------
// Aggregation: one warp per destination node. Lane owns one float4 column
// slice (32 x 16B = 512B row). Accumulate neighbor message rows in registers,
// single store. Unroll-4 over neighbors for MLP.
//   msg: m-half base (already +128 floats), row stride 256 floats.
//   agg: agg-half base (col 0), row stride 256 floats.
// ---------------------------------------------------------------------------
__global__ __launch_bounds__(256)
void gather_kernel(const float* __restrict__ msg,
                   float* __restrict__ agg,
                   const int* __restrict__ row_start,
                   const int* __restrict__ edge_src,
                   int n)
{
    int w    = (blockIdx.x * blockDim.x + threadIdx.x) >> 5;
    int lane = threadIdx.x & 31;
    if (w >= n) return;

    const int start = __ldg(row_start + w);
    const int end   = __ldg(row_start + w + 1);

    const float4* mb = reinterpret_cast<const float4*>(msg);
    float4 a0 = make_float4(0.f, 0.f, 0.f, 0.f);
    float4 a1 = make_float4(0.f, 0.f, 0.f, 0.f);

    int j = start;
    for (; j + 4 <= end; j += 4) {
        int s0 = __ldg(edge_src + j);
        int s1 = __ldg(edge_src + j + 1);
        int s2 = __ldg(edge_src + j + 2);
        int s3 = __ldg(edge_src + j + 3);
        float4 v0 = __ldg(mb + (size_t)s0 * (LDC / 4) + lane);
        float4 v1 = __ldg(mb + (size_t)s1 * (LDC / 4) + lane);
        float4 v2 = __ldg(mb + (size_t)s2 * (LDC / 4) + lane);
        float4 v3 = __ldg(mb + (size_t)s3 * (LDC / 4) + lane);
        a0.x += v0.x; a0.y += v0.y; a0.z += v0.z; a0.w += v0.w;
        a1.x += v1.x; a1.y += v1.y; a1.z += v1.z; a1.w += v1.w;
        a0.x += v2.x; a0.y += v2.y; a0.z += v2.z; a0.w += v2.w;
        a1.x += v3.x; a1.y += v3.y; a1.z += v3.z; a1.w += v3.w;
    }
    for (; j < end; j++) {
        int s = __ldg(edge_src + j);
        float4 v = __ldg(mb + (size_t)s * (LDC / 4) + lane);
        a0.x += v.x; a0.y += v.y; a0.z += v.z; a0.w += v.w;
    }

    float4 r;
    r.x = a0.x + a1.x; r.y = a0.y + a1.y; r.z = a0.z + a1.z; r.w = a0.w + a1.w;
    *(reinterpret_cast<float4*>(agg) + (size_t)w * (LDC / 4) + lane) = r;
}

// ---------------------------------------------------------------------------
// SGEMM: C[row, 128+col] = sum_k A[row,k] * W[k,col] + bias[col]
// Block: 256 threads, tile 128x128, 8x8 per thread, K-tile 16.
// (agg half is fully overwritten by gather_kernel; no zeroing needed)
// ---------------------------------------------------------------------------
__global__ __launch_bounds__(256)
void gemm_bias(const float* __restrict__ A, int lda,
               const float* __restrict__ W,
               const float* __restrict__ bias,
               float* __restrict__ C,
               int M, int K)
{
    __shared__ float As[16][132];
    __shared__ float Bs[16][128];

    const int t  = threadIdx.x;
    const int tx = t & 15;
    const int ty = t >> 4;
    const int row0 = blockIdx.x * 128;

    float acc[8][8];
#pragma unroll
    for (int i = 0; i < 8; i++)
#pragma unroll
        for (int j = 0; j < 8; j++) acc[i][j] = 0.0f;

    for (int k0 = 0; k0 < K; k0 += 16) {
#pragma unroll
        for (int l = 0; l < 2; l++) {
            int idx = t + l * 256;
            int row = idx >> 2;
            int f4  = idx & 3;
            int gr  = row0 + row;
            float4 v = make_float4(0.f, 0.f, 0.f, 0.f);
            if (gr < M)
                v = *reinterpret_cast<const float4*>(A + (size_t)gr * lda + k0 + f4 * 4);
            As[f4 * 4 + 0][row] = v.x;
            As[f4 * 4 + 1][row] = v.y;
            As[f4 * 4 + 2][row] = v.z;
            As[f4 * 4 + 3][row] = v.w;
        }
#pragma unroll
        for (int l = 0; l < 2; l++) {
            int idx = t + l * 256;
            int k   = idx >> 5;
            int c4  = idx & 31;
            *reinterpret_cast<float4*>(&Bs[k][c4 * 4]) =
                *reinterpret_cast<const float4*>(W + (size_t)(k0 + k) * 128 + c4 * 4);
        }
        __syncthreads();

#pragma unroll
        for (int kk = 0; kk < 16; kk++) {
            float a[8], b[8];
            *reinterpret_cast<float4*>(a)     = *reinterpret_cast<const float4*>(&As[kk][ty * 8]);
            *reinterpret_cast<float4*>(a + 4) = *reinterpret_cast<const float4*>(&As[kk][ty * 8 + 4]);
            *reinterpret_cast<float4*>(b)     = *reinterpret_cast<const float4*>(&Bs[kk][tx * 8]);
            *reinterpret_cast<float4*>(b + 4) = *reinterpret_cast<const float4*>(&Bs[kk][tx * 8 + 4]);
#pragma unroll
            for (int i = 0; i < 8; i++)
#pragma unroll
                for (int j = 0; j < 8; j++)
                    acc[i][j] = fmaf(a[i], b[j], acc[i][j]);
        }
        __syncthreads();
    }

    float bl[8];
    *reinterpret_cast<float4*>(bl)     = *reinterpret_cast<const float4*>(bias + tx * 8);
    *reinterpret_cast<float4*>(bl + 4) = *reinterpret_cast<const float4*>(bias + tx * 8 + 4);

#pragma unroll
    for (int i = 0; i < 8; i++) {
        int gr = row0 + ty * 8 + i;
        if (gr >= M) continue;
        float* crow = C + (size_t)gr * LDC;
        float4 v0, v1;
        v0.x = acc[i][0] + bl[0]; v0.y = acc[i][1] + bl[1];
        v0.z = acc[i][2] + bl[2]; v0.w = acc[i][3] + bl[3];
        v1.x = acc[i][4] + bl[4]; v1.y = acc[i][5] + bl[5];
        v1.z = acc[i][6] + bl[6]; v1.w = acc[i][7] + bl[7];
        *reinterpret_cast<float4*>(crow + 128 + tx * 8)     = v0;
        *reinterpret_cast<float4*>(crow + 128 + tx * 8 + 4) = v1;
    }
}

// ---------------------------------------------------------------------------
// Launch
// ---------------------------------------------------------------------------
extern "C" void kernel_launch(void* const* d_in, const int* in_sizes, int n_in,
                              void* d_out, int out_size)
{
    const float* features = (const float*)d_in[0];
    const int*   src      = (const int*)  d_in[1];
    const int*   dst      = (const int*)  d_in[2];
    const float* W1       = (const float*)d_in[3];
    const float* b1       = (const float*)d_in[4];
    const float* W2       = (const float*)d_in[5];
    const float* b2       = (const float*)d_in[6];
    float*       out      = (float*)d_out;

    const int M = in_sizes[0] / 128;   // 50000 nodes
    const int E = in_sizes[1];         // 800000 edges

    float *feat1; int *cnt, *row_start, *cursor, *edge_src;
    cudaGetSymbolAddress((void**)&feat1,     g_feat1);
    cudaGetSymbolAddress((void**)&cnt,       g_cnt);
    cudaGetSymbolAddress((void**)&row_start, g_row_start);
    cudaGetSymbolAddress((void**)&cursor,    g_cursor);
    cudaGetSymbolAddress((void**)&edge_src,  g_edge_src);

    const int gemm_blocks   = (M + 127) / 128;   // 391
    const int edge_blocks   = (E + 255) / 256;   // 3125
    const int gather_blocks = (M + 7) / 8;       // 8 warps/block, 1 node/warp

    // --- CSR build (edges shared by both layers) ---
    cudaMemsetAsync(cnt, 0, (size_t)(M + 1) * sizeof(int));
    hist_kernel<<<edge_blocks, 256>>>(dst, cnt, E);
    scan_kernel<<<1, 1024>>>(cnt, row_start, cursor, M);
    fill_kernel<<<edge_blocks, 256>>>(src, dst, cursor, edge_src, E);

    // --- Layer 1 ---
    gemm_bias<<<gemm_blocks, 256>>>(features, 128, W1, b1, feat1, M, 128);
    gather_kernel<<<gather_blocks, 256>>>(feat1 + 128, feat1, row_start, edge_src, M);

    // --- Layer 2 ---
    gemm_bias<<<gemm_blocks, 256>>>(feat1, 256, W2, b2, out, M, 256);
    gather_kernel<<<gather_blocks, 256>>>(out + 128, out, row_start, edge_src, M);
}

// round 6
// speedup vs baseline: 1.2162x; 1.1142x over previous
#include <cuda_runtime.h>
#include <cuda_bf16.h>
#include <cstdint>

// ---------------------------------------------------------------------------
// GNN_85366769975686  (R5: 3xTF32 mma.sync GEMM + CSR-gather aggregation)
//   layer(feat, W, b): m = feat@W + b ; agg = segment_sum(m[src], dst)
//                      return concat([agg, m], -1)
// N = 50000 nodes, E = 800000 edges, D = 128, output [N, 256] fp32.
// NOTE: tcgen05 is unusable (harness compiles PTX at compute_103, not 103a),
// so tensor cores are driven through sm_80 mma.sync (HMMA fallback path).
// ---------------------------------------------------------------------------

#define N_MAX     50048
#define E_MAX     800000
#define LDC       256            // row stride (floats) of concat buffers

// Scratch (static — no allocations allowed)
__device__ float g_feat1[(size_t)N_MAX * LDC];      // layer-1 concat buffer
__device__ int   g_cnt[N_MAX + 1];
__device__ int   g_row_start[N_MAX + 1];
__device__ int   g_cursor[N_MAX + 1];
__device__ int   g_edge_src[E_MAX];
// W split into tf32 hi/lo, transposed to [n=128][K] ("col" operand layout)
__device__ uint32_t g_B1hi[128 * 128];
__device__ uint32_t g_B1lo[128 * 128];
__device__ uint32_t g_B2hi[128 * 256];
__device__ uint32_t g_B2lo[128 * 256];

// ---------------------------------------------------------------------------
// helpers
// ---------------------------------------------------------------------------
__device__ __forceinline__ uint32_t tf32_round(float x) {
    uint32_t r;
    asm("cvt.rna.tf32.f32 %0, %1;" : "=r"(r) : "f"(x));
    return r;
}

__device__ __forceinline__ void mma_tf32(float* d, const uint32_t* a,
                                         const uint32_t b0, const uint32_t b1) {
    asm volatile(
        "mma.sync.aligned.m16n8k8.row.col.f32.tf32.tf32.f32 "
        "{%0,%1,%2,%3}, {%4,%5,%6,%7}, {%8,%9}, {%0,%1,%2,%3};"
        : "+f"(d[0]), "+f"(d[1]), "+f"(d[2]), "+f"(d[3])
        : "r"(a[0]), "r"(a[1]), "r"(a[2]), "r"(a[3]), "r"(b0), "r"(b1));
}

// ---------------------------------------------------------------------------
// Prep: split W[K,128] into tf32 hi/lo and transpose to [n=128][K]
// ---------------------------------------------------------------------------
__global__ void split_w_kernel(const float* __restrict__ W,
                               uint32_t* __restrict__ Bhi,
                               uint32_t* __restrict__ Blo, int K)
{
    int i = blockIdx.x * blockDim.x + threadIdx.x;
    if (i < K * 128) {
        int k = i >> 7;
        int n = i & 127;
        float w = W[i];
        uint32_t hb = tf32_round(w);
        float h = __uint_as_float(hb);
        Bhi[n * K + k] = hb;
        Blo[n * K + k] = tf32_round(w - h);
    }
}

// ---------------------------------------------------------------------------
// 3xTF32 mma.sync GEMM: C[row, 128+col] = sum_k A[row,k]*W[k,col] + bias[col]
// CTA: 256 threads, tile 128(M) x 128(N), K-chunk 32.
// Warps: 4(M) x 2(N); warp tile 32 x 64; mma m16n8k8.
// Smem rows padded to 36 floats -> fragment LDS is bank-conflict-free
// (bank = (4*g + tg) % 32 hits all 32 banks across a warp).
// ---------------------------------------------------------------------------
#define SPAD 36
#define SM_AHI 0
#define SM_ALO (128 * SPAD)
#define SM_BHI (2 * 128 * SPAD)
#define SM_BLO (3 * 128 * SPAD)
#define GEMM_SMEM_BYTES (4 * 128 * SPAD * 4)

__global__ __launch_bounds__(256)
void gemm_tc(const float* __restrict__ A, int lda,
             const uint32_t* __restrict__ Bhi, const uint32_t* __restrict__ Blo,
             const float* __restrict__ bias,
             float* __restrict__ C, int M, int K)
{
    extern __shared__ uint32_t sm[];

    const int tid  = threadIdx.x;
    const int wid  = tid >> 5;
    const int lane = tid & 31;
    const int g    = lane >> 2;      // group id (row within fragment)
    const int tg   = lane & 3;       // thread-in-group (col within fragment)
    const int wm   = wid & 3;        // warp M index (0..3)
    const int wn   = wid >> 2;       // warp N index (0..1)
    const int row0 = blockIdx.x * 128;

    float d[2][8][4];                // [m-frag][n-frag][c0..c3]
#pragma unroll
    for (int i = 0; i < 2; i++)
#pragma unroll
        for (int j = 0; j < 8; j++)
#pragma unroll
            for (int c = 0; c < 4; c++) d[i][j][c] = 0.0f;

    const int nch = K >> 5;
    for (int kc = 0; kc < nch; kc++) {
        const int kbase = kc * 32;

        // ---- stage chunk into smem: A split hi/lo on the fly, B copied ----
#pragma unroll
        for (int l = 0; l < 4; l++) {
            int idx = tid + l * 256;     // 1024 float4 slots
            int row = idx >> 3;          // 0..127
            int c4  = idx & 7;           // 8 float4 per 32-float row
            int so  = row * SPAD + c4 * 4;

            int gr = row0 + row;
            float4 v = make_float4(0.f, 0.f, 0.f, 0.f);
            if (gr < M)
                v = *reinterpret_cast<const float4*>(A + (size_t)gr * lda + kbase + c4 * 4);
            uint4 h, o;
            h.x = tf32_round(v.x); o.x = tf32_round(v.x - __uint_as_float(h.x));
            h.y = tf32_round(v.y); o.y = tf32_round(v.y - __uint_as_float(h.y));
            h.z = tf32_round(v.z); o.z = tf32_round(v.z - __uint_as_float(h.z));
            h.w = tf32_round(v.w); o.w = tf32_round(v.w - __uint_as_float(h.w));
            *reinterpret_cast<uint4*>(sm + SM_AHI + so) = h;
            *reinterpret_cast<uint4*>(sm + SM_ALO + so) = o;

            const size_t bofs = (size_t)row * K + kbase + c4 * 4;
            *reinterpret_cast<uint4*>(sm + SM_BHI + so) =
                *reinterpret_cast<const uint4*>(Bhi + bofs);
            *reinterpret_cast<uint4*>(sm + SM_BLO + so) =
                *reinterpret_cast<const uint4*>(Blo + bofs);
        }
        __syncthreads();

        // ---- compute: 4 k8 steps ----
#pragma unroll
        for (int ks = 0; ks < 4; ks++) {
            const int kk = ks * 8;
            // A fragments for both m-frags, hi and lo
            uint32_t ah[2][4], al[2][4];
#pragma unroll
            for (int mf = 0; mf < 2; mf++) {
                int r0 = (wm * 32 + mf * 16 + g) * SPAD + kk + tg;
                int r8 = r0 + 8 * SPAD;
                ah[mf][0] = sm[SM_AHI + r0];
                ah[mf][1] = sm[SM_AHI + r8];
                ah[mf][2] = sm[SM_AHI + r0 + 4];
                ah[mf][3] = sm[SM_AHI + r8 + 4];
                al[mf][0] = sm[SM_ALO + r0];
                al[mf][1] = sm[SM_ALO + r8];
                al[mf][2] = sm[SM_ALO + r0 + 4];
                al[mf][3] = sm[SM_ALO + r8 + 4];
            }
            // stream B fragments per n-frag (keeps register count down)
#pragma unroll
            for (int nf = 0; nf < 8; nf++) {
                int b0o = (wn * 64 + nf * 8 + g) * SPAD + kk + tg;
                uint32_t bh0 = sm[SM_BHI + b0o];
                uint32_t bh1 = sm[SM_BHI + b0o + 4];
                uint32_t bl0 = sm[SM_BLO + b0o];
                uint32_t bl1 = sm[SM_BLO + b0o + 4];
#pragma unroll
                for (int mf = 0; mf < 2; mf++) {
                    mma_tf32(d[mf][nf], ah[mf], bh0, bh1);
                    mma_tf32(d[mf][nf], al[mf], bh0, bh1);
                    mma_tf32(d[mf][nf], ah[mf], bl0, bl1);
                }
            }
        }
        __syncthreads();
    }

    // ---- epilogue: + bias, write C[:, 128..256) ----
#pragma unroll
    for (int nf = 0; nf < 8; nf++) {
        const int col = wn * 64 + nf * 8 + tg * 2;
        const float b0 = __ldg(bias + col);
        const float b1 = __ldg(bias + col + 1);
#pragma unroll
        for (int mf = 0; mf < 2; mf++) {
            int r = row0 + wm * 32 + mf * 16 + g;
            if (r < M) {
                float2 v0 = make_float2(d[mf][nf][0] + b0, d[mf][nf][1] + b1);
                *reinterpret_cast<float2*>(C + (size_t)r * LDC + 128 + col) = v0;
            }
            if (r + 8 < M) {
                float2 v1 = make_float2(d[mf][nf][2] + b0, d[mf][nf][3] + b1);
                *reinterpret_cast<float2*>(C + (size_t)(r + 8) * LDC + 128 + col) = v1;
            }
        }
    }
}

// ---------------------------------------------------------------------------
// CSR build
// ---------------------------------------------------------------------------
__global__ void hist_kernel(const int* __restrict__ dst, int* __restrict__ cnt, int E)
{
    int e = blockIdx.x * blockDim.x + threadIdx.x;
    if (e < E) atomicAdd(&cnt[__ldg(dst + e)], 1);
}

__global__ __launch_bounds__(1024)
void scan_kernel(const int* __restrict__ cnt,
                 int* __restrict__ row_start,
                 int* __restrict__ cursor, int n)
{
    __shared__ int sums[1024];
    const int t = threadIdx.x;
    const int chunk = (n + 1023) / 1024;
    const int lo = t * chunk;
    const int hi = min(lo + chunk, n);

    int s = 0;
    for (int i = lo; i < hi; i++) s += cnt[i];
    sums[t] = s;
    __syncthreads();

#pragma unroll
    for (int off = 1; off < 1024; off <<= 1) {
        int u = (t >= off) ? sums[t - off] : 0;
        __syncthreads();
        sums[t] += u;
        __syncthreads();
    }

    int run = sums[t] - s;
    for (int i = lo; i < hi; i++) {
        row_start[i] = run;
        cursor[i]    = run;
        run += cnt[i];
    }
    if (t == 1023) row_start[n] = sums[1023];
}

__global__ void fill_kernel(const int* __restrict__ src, const int* __restrict__ dst,
                            int* __restrict__ cursor, int* __restrict__ edge_src, int E)
{
    int e = blockIdx.x * blockDim.x + threadIdx.x;
    if (e < E) {
        int p = atomicAdd(&cursor[__ldg(dst + e)], 1);
        edge_src[p] = __ldg(src + e);
    }
}

// ---------------------------------------------------------------------------
// Aggregation: one warp per destination node (register accumulation, 1 store)
// ---------------------------------------------------------------------------
__global__ __launch_bounds__(256)
void gather_kernel(const float* __restrict__ msg,
                   float* __restrict__ agg,
                   const int* __restrict__ row_start,
                   const int* __restrict__ edge_src,
                   int n)
{
    int w    = (blockIdx.x * blockDim.x + threadIdx.x) >> 5;
    int lane = threadIdx.x & 31;
    if (w >= n) return;

    const int start = __ldg(row_start + w);
    const int end   = __ldg(row_start + w + 1);

    const float4* mb = reinterpret_cast<const float4*>(msg);
    float4 a0 = make_float4(0.f, 0.f, 0.f, 0.f);
    float4 a1 = make_float4(0.f, 0.f, 0.f, 0.f);

    int j = start;
    for (; j + 4 <= end; j += 4) {
        int s0 = __ldg(edge_src + j);
        int s1 = __ldg(edge_src + j + 1);
        int s2 = __ldg(edge_src + j + 2);
        int s3 = __ldg(edge_src + j + 3);
        float4 v0 = __ldg(mb + (size_t)s0 * (LDC / 4) + lane);
        float4 v1 = __ldg(mb + (size_t)s1 * (LDC / 4) + lane);
        float4 v2 = __ldg(mb + (size_t)s2 * (LDC / 4) + lane);
        float4 v3 = __ldg(mb + (size_t)s3 * (LDC / 4) + lane);
        a0.x += v0.x; a0.y += v0.y; a0.z += v0.z; a0.w += v0.w;
        a1.x += v1.x; a1.y += v1.y; a1.z += v1.z; a1.w += v1.w;
        a0.x += v2.x; a0.y += v2.y; a0.z += v2.z; a0.w += v2.w;
        a1.x += v3.x; a1.y += v3.y; a1.z += v3.z; a1.w += v3.w;
    }
    for (; j < end; j++) {
        int s = __ldg(edge_src + j);
        float4 v = __ldg(mb + (size_t)s * (LDC / 4) + lane);
        a0.x += v.x; a0.y += v.y; a0.z += v.z; a0.w += v.w;
    }

    float4 r;
    r.x = a0.x + a1.x; r.y = a0.y + a1.y; r.z = a0.z + a1.z; r.w = a0.w + a1.w;
    *(reinterpret_cast<float4*>(agg) + (size_t)w * (LDC / 4) + lane) = r;
}

// ---------------------------------------------------------------------------
// Launch
// ---------------------------------------------------------------------------
extern "C" void kernel_launch(void* const* d_in, const int* in_sizes, int n_in,
                              void* d_out, int out_size)
{
    const float* features = (const float*)d_in[0];
    const int*   src      = (const int*)  d_in[1];
    const int*   dst      = (const int*)  d_in[2];
    const float* W1       = (const float*)d_in[3];
    const float* b1       = (const float*)d_in[4];
    const float* W2       = (const float*)d_in[5];
    const float* b2       = (const float*)d_in[6];
    float*       out      = (float*)d_out;

    const int M = in_sizes[0] / 128;   // 50000 nodes
    const int E = in_sizes[1];         // 800000 edges

    float *feat1;
    uint32_t *B1hi, *B1lo, *B2hi, *B2lo;
    int *cnt, *row_start, *cursor, *edge_src;
    cudaGetSymbolAddress((void**)&feat1,     g_feat1);
    cudaGetSymbolAddress((void**)&cnt,       g_cnt);
    cudaGetSymbolAddress((void**)&row_start, g_row_start);
    cudaGetSymbolAddress((void**)&cursor,    g_cursor);
    cudaGetSymbolAddress((void**)&edge_src,  g_edge_src);
    cudaGetSymbolAddress((void**)&B1hi,      g_B1hi);
    cudaGetSymbolAddress((void**)&B1lo,      g_B1lo);
    cudaGetSymbolAddress((void**)&B2hi,      g_B2hi);
    cudaGetSymbolAddress((void**)&B2lo,      g_B2lo);

    cudaFuncSetAttribute(gemm_tc, cudaFuncAttributeMaxDynamicSharedMemorySize,
                         GEMM_SMEM_BYTES);

    const int gemm_blocks   = (M + 127) / 128;   // 391
    const int edge_blocks   = (E + 255) / 256;
    const int gather_blocks = (M + 7) / 8;

    // --- W split/transpose (tiny) ---
    split_w_kernel<<<(128 * 128 + 255) / 256, 256>>>(W1, B1hi, B1lo, 128);
    split_w_kernel<<<(256 * 128 + 255) / 256, 256>>>(W2, B2hi, B2lo, 256);

    // --- CSR build (edges shared by both layers) ---
    cudaMemsetAsync(cnt, 0, (size_t)(M + 1) * sizeof(int));
    hist_kernel<<<edge_blocks, 256>>>(dst, cnt, E);
    scan_kernel<<<1, 1024>>>(cnt, row_start, cursor, M);
    fill_kernel<<<edge_blocks, 256>>>(src, dst, cursor, edge_src, E);

    // --- Layer 1 ---
    gemm_tc<<<gemm_blocks, 256, GEMM_SMEM_BYTES>>>(features, 128, B1hi, B1lo,
                                                   b1, feat1, M, 128);
    gather_kernel<<<gather_blocks, 256>>>(feat1 + 128, feat1, row_start, edge_src, M);

    // --- Layer 2 ---
    gemm_tc<<<gemm_blocks, 256, GEMM_SMEM_BYTES>>>(feat1, 256, B2hi, B2lo,
                                                   b2, out, M, 256);
    gather_kernel<<<gather_blocks, 256>>>(out + 128, out, row_start, edge_src, M);
}

// round 7
// speedup vs baseline: 1.5781x; 1.2975x over previous
#include <cuda_runtime.h>
#include <cuda_bf16.h>
#include <cstdint>

// ---------------------------------------------------------------------------
// GNN_85366769975686  (R6: parallel CSR scan + 3xTF32 mma.sync GEMM + gather)
//   layer(feat, W, b): m = feat@W + b ; agg = segment_sum(m[src], dst)
//                      return concat([agg, m], -1)
// N = 50000 nodes, E = 800000 edges, D = 128, output [N, 256] fp32.
// tcgen05 unusable (harness emits compute_103 PTX); tensor via sm_80 mma.sync.
// ---------------------------------------------------------------------------

#define N_MAX     50048
#define E_MAX     800000
#define LDC       256            // row stride (floats) of concat buffers
#define SCAN_B    256            // elements per scan block
#define SCAN_GRID ((N_MAX + SCAN_B - 1) / SCAN_B)   // 196

// Scratch (static — no allocations allowed)
__device__ float g_feat1[(size_t)N_MAX * LDC];      // layer-1 concat buffer
__device__ int   g_cnt[N_MAX + 1];
__device__ int   g_row_start[N_MAX + 1];
__device__ int   g_cursor[N_MAX + 1];
__device__ int   g_edge_src[E_MAX];
__device__ int   g_bsum[SCAN_GRID];                 // per-block sums
__device__ int   g_boff[SCAN_GRID];                 // exclusive block offsets
// W split into tf32 hi/lo, transposed to [n=128][K] ("col" operand layout)
__device__ uint32_t g_B1hi[128 * 128];
__device__ uint32_t g_B1lo[128 * 128];
__device__ uint32_t g_B2hi[128 * 256];
__device__ uint32_t g_B2lo[128 * 256];

// ---------------------------------------------------------------------------
// helpers
// ---------------------------------------------------------------------------
__device__ __forceinline__ uint32_t tf32_round(float x) {
    uint32_t r;
    asm("cvt.rna.tf32.f32 %0, %1;" : "=r"(r) : "f"(x));
    return r;
}

__device__ __forceinline__ void mma_tf32(float* d, const uint32_t* a,
                                         const uint32_t b0, const uint32_t b1) {
    asm volatile(
        "mma.sync.aligned.m16n8k8.row.col.f32.tf32.tf32.f32 "
        "{%0,%1,%2,%3}, {%4,%5,%6,%7}, {%8,%9}, {%0,%1,%2,%3};"
        : "+f"(d[0]), "+f"(d[1]), "+f"(d[2]), "+f"(d[3])
        : "r"(a[0]), "r"(a[1]), "r"(a[2]), "r"(a[3]), "r"(b0), "r"(b1));
}

// ---------------------------------------------------------------------------
// Prep: split W[K,128] into tf32 hi/lo and transpose to [n=128][K]
// ---------------------------------------------------------------------------
__global__ void split_w_kernel(const float* __restrict__ W,
                               uint32_t* __restrict__ Bhi,
                               uint32_t* __restrict__ Blo, int K)
{
    int i = blockIdx.x * blockDim.x + threadIdx.x;
    if (i < K * 128) {
        int k = i >> 7;
        int n = i & 127;
        float w = W[i];
        uint32_t hb = tf32_round(w);
        float h = __uint_as_float(hb);
        Bhi[n * K + k] = hb;
        Blo[n * K + k] = tf32_round(w - h);
    }
}

// ---------------------------------------------------------------------------
// 3xTF32 mma.sync GEMM (unchanged from R5)
// ---------------------------------------------------------------------------
#define SPAD 36
#define SM_AHI 0
#define SM_ALO (128 * SPAD)
#define SM_BHI (2 * 128 * SPAD)
#define SM_BLO (3 * 128 * SPAD)
#define GEMM_SMEM_BYTES (4 * 128 * SPAD * 4)

__global__ __launch_bounds__(256)
void gemm_tc(const float* __restrict__ A, int lda,
             const uint32_t* __restrict__ Bhi, const uint32_t* __restrict__ Blo,
             const float* __restrict__ bias,
             float* __restrict__ C, int M, int K)
{
    extern __shared__ uint32_t sm[];

    const int tid  = threadIdx.x;
    const int wid  = tid >> 5;
    const int lane = tid & 31;
    const int g    = lane >> 2;
    const int tg   = lane & 3;
    const int wm   = wid & 3;
    const int wn   = wid >> 2;
    const int row0 = blockIdx.x * 128;

    float d[2][8][4];
#pragma unroll
    for (int i = 0; i < 2; i++)
#pragma unroll
        for (int j = 0; j < 8; j++)
#pragma unroll
            for (int c = 0; c < 4; c++) d[i][j][c] = 0.0f;

    const int nch = K >> 5;
    for (int kc = 0; kc < nch; kc++) {
        const int kbase = kc * 32;
#pragma unroll
        for (int l = 0; l < 4; l++) {
            int idx = tid + l * 256;
            int row = idx >> 3;
            int c4  = idx & 7;
            int so  = row * SPAD + c4 * 4;

            int gr = row0 + row;
            float4 v = make_float4(0.f, 0.f, 0.f, 0.f);
            if (gr < M)
                v = *reinterpret_cast<const float4*>(A + (size_t)gr * lda + kbase + c4 * 4);
            uint4 h, o;
            h.x = tf32_round(v.x); o.x = tf32_round(v.x - __uint_as_float(h.x));
            h.y = tf32_round(v.y); o.y = tf32_round(v.y - __uint_as_float(h.y));
            h.z = tf32_round(v.z); o.z = tf32_round(v.z - __uint_as_float(h.z));
            h.w = tf32_round(v.w); o.w = tf32_round(v.w - __uint_as_float(h.w));
            *reinterpret_cast<uint4*>(sm + SM_AHI + so) = h;
            *reinterpret_cast<uint4*>(sm + SM_ALO + so) = o;

            const size_t bofs = (size_t)row * K + kbase + c4 * 4;
            *reinterpret_cast<uint4*>(sm + SM_BHI + so) =
                *reinterpret_cast<const uint4*>(Bhi + bofs);
            *reinterpret_cast<uint4*>(sm + SM_BLO + so) =
                *reinterpret_cast<const uint4*>(Blo + bofs);
        }
        __syncthreads();

#pragma unroll
        for (int ks = 0; ks < 4; ks++) {
            const int kk = ks * 8;
            uint32_t ah[2][4], al[2][4];
#pragma unroll
            for (int mf = 0; mf < 2; mf++) {
                int r0 = (wm * 32 + mf * 16 + g) * SPAD + kk + tg;
                int r8 = r0 + 8 * SPAD;
                ah[mf][0] = sm[SM_AHI + r0];
                ah[mf][1] = sm[SM_AHI + r8];
                ah[mf][2] = sm[SM_AHI + r0 + 4];
                ah[mf][3] = sm[SM_AHI + r8 + 4];
                al[mf][0] = sm[SM_ALO + r0];
                al[mf][1] = sm[SM_ALO + r8];
                al[mf][2] = sm[SM_ALO + r0 + 4];
                al[mf][3] = sm[SM_ALO + r8 + 4];
            }
#pragma unroll
            for (int nf = 0; nf < 8; nf++) {
                int b0o = (wn * 64 + nf * 8 + g) * SPAD + kk + tg;
                uint32_t bh0 = sm[SM_BHI + b0o];
                uint32_t bh1 = sm[SM_BHI + b0o + 4];
                uint32_t bl0 = sm[SM_BLO + b0o];
                uint32_t bl1 = sm[SM_BLO + b0o + 4];
#pragma unroll
                for (int mf = 0; mf < 2; mf++) {
                    mma_tf32(d[mf][nf], ah[mf], bh0, bh1);
                    mma_tf32(d[mf][nf], al[mf], bh0, bh1);
                    mma_tf32(d[mf][nf], ah[mf], bl0, bl1);
                }
            }
        }
        __syncthreads();
    }

#pragma unroll
    for (int nf = 0; nf < 8; nf++) {
        const int col = wn * 64 + nf * 8 + tg * 2;
        const float b0 = __ldg(bias + col);
        const float b1 = __ldg(bias + col + 1);
#pragma unroll
        for (int mf = 0; mf < 2; mf++) {
            int r = row0 + wm * 32 + mf * 16 + g;
            if (r < M) {
                float2 v0 = make_float2(d[mf][nf][0] + b0, d[mf][nf][1] + b1);
                *reinterpret_cast<float2*>(C + (size_t)r * LDC + 128 + col) = v0;
            }
            if (r + 8 < M) {
                float2 v1 = make_float2(d[mf][nf][2] + b0, d[mf][nf][3] + b1);
                *reinterpret_cast<float2*>(C + (size_t)(r + 8) * LDC + 128 + col) = v1;
            }
        }
    }
}

// ---------------------------------------------------------------------------
// CSR build: histogram
// ---------------------------------------------------------------------------
__global__ void hist_kernel(const int* __restrict__ dst, int* __restrict__ cnt, int E)
{
    int e = blockIdx.x * blockDim.x + threadIdx.x;
    if (e < E) atomicAdd(&cnt[__ldg(dst + e)], 1);
}

// ---------------------------------------------------------------------------
// Parallel exclusive scan over n counts (3 phases)
// ---------------------------------------------------------------------------
// Phase 1: per-block sums (256 elements per block)
__global__ __launch_bounds__(SCAN_B)
void reduce_kernel(const int* __restrict__ cnt, int* __restrict__ bsum, int n)
{
    __shared__ int ws[8];
    const int tid = threadIdx.x;
    const int i   = blockIdx.x * SCAN_B + tid;
    int v = (i < n) ? cnt[i] : 0;
#pragma unroll
    for (int o = 16; o > 0; o >>= 1) v += __shfl_down_sync(0xffffffffu, v, o);
    if ((tid & 31) == 0) ws[tid >> 5] = v;
    __syncthreads();
    if (tid < 8) {
        int s = ws[tid];
#pragma unroll
        for (int o = 4; o > 0; o >>= 1) s += __shfl_down_sync(0xffu, s, o);
        if (tid == 0) bsum[blockIdx.x] = s;
    }
}

// Phase 2: single-block exclusive scan of block sums (nb <= 256)
__global__ __launch_bounds__(SCAN_B)
void scan_sums_kernel(const int* __restrict__ bsum, int* __restrict__ boff, int nb)
{
    __shared__ int ws[8];
    const int tid  = threadIdx.x;
    const int lane = tid & 31;
    const int w    = tid >> 5;
    int c = (tid < nb) ? bsum[tid] : 0;
    int v = c;
#pragma unroll
    for (int o = 1; o < 32; o <<= 1) {
        int u = __shfl_up_sync(0xffffffffu, v, o);
        if (lane >= o) v += u;
    }
    if (lane == 31) ws[w] = v;
    __syncthreads();
    if (tid < 8) {
        int s = ws[tid];
        int t = s;
#pragma unroll
        for (int o = 1; o < 8; o <<= 1) {
            int u = __shfl_up_sync(0xffu, t, o);
            if (tid >= o) t += u;
        }
        ws[tid] = t - s;   // exclusive warp offset
    }
    __syncthreads();
    if (tid < nb) boff[tid] = v - c + ws[w];
}

// Phase 3: block-local exclusive scan + block offset -> row_start, cursor
__global__ __launch_bounds__(SCAN_B)
void downsweep_kernel(const int* __restrict__ cnt, const int* __restrict__ boff,
                      int* __restrict__ row_start, int* __restrict__ cursor, int n)
{
    __shared__ int ws[8];
    const int tid  = threadIdx.x;
    const int lane = tid & 31;
    const int w    = tid >> 5;
    const int i    = blockIdx.x * SCAN_B + tid;
    int c = (i < n) ? cnt[i] : 0;
    int v = c;
#pragma unroll
    for (int o = 1; o < 32; o <<= 1) {
        int u = __shfl_up_sync(0xffffffffu, v, o);
        if (lane >= o) v += u;
    }
    if (lane == 31) ws[w] = v;
    __syncthreads();
    if (tid < 8) {
        int s = ws[tid];
        int t = s;
#pragma unroll
        for (int o = 1; o < 8; o <<= 1) {
            int u = __shfl_up_sync(0xffu, t, o);
            if (tid >= o) t += u;
        }
        ws[tid] = t - s;
    }
    __syncthreads();
    if (i < n) {
        int ex = boff[blockIdx.x] + ws[w] + v - c;
        row_start[i] = ex;
        cursor[i]    = ex;
        if (i == n - 1) row_start[n] = ex + c;
    }
}

// ---------------------------------------------------------------------------
// CSR build: fill buckets
// ---------------------------------------------------------------------------
__global__ void fill_kernel(const int* __restrict__ src, const int* __restrict__ dst,
                            int* __restrict__ cursor, int* __restrict__ edge_src, int E)
{
    int e = blockIdx.x * blockDim.x + threadIdx.x;
    if (e < E) {
        int p = atomicAdd(&cursor[__ldg(dst + e)], 1);
        edge_src[p] = __ldg(src + e);
    }
}

// ---------------------------------------------------------------------------
// Aggregation: one warp per destination node (register accumulation, 1 store)
// ---------------------------------------------------------------------------
__global__ __launch_bounds__(256)
void gather_kernel(const float* __restrict__ msg,
                   float* __restrict__ agg,
                   const int* __restrict__ row_start,
                   const int* __restrict__ edge_src,
                   int n)
{
    int w    = (blockIdx.x * blockDim.x + threadIdx.x) >> 5;
    int lane = threadIdx.x & 31;
    if (w >= n) return;

    const int start = __ldg(row_start + w);
    const int end   = __ldg(row_start + w + 1);

    const float4* mb = reinterpret_cast<const float4*>(msg);
    float4 a0 = make_float4(0.f, 0.f, 0.f, 0.f);
    float4 a1 = make_float4(0.f, 0.f, 0.f, 0.f);

    int j = start;
    for (; j + 4 <= end; j += 4) {
        int s0 = __ldg(edge_src + j);
        int s1 = __ldg(edge_src + j + 1);
        int s2 = __ldg(edge_src + j + 2);
        int s3 = __ldg(edge_src + j + 3);
        float4 v0 = __ldg(mb + (size_t)s0 * (LDC / 4) + lane);
        float4 v1 = __ldg(mb + (size_t)s1 * (LDC / 4) + lane);
        float4 v2 = __ldg(mb + (size_t)s2 * (LDC / 4) + lane);
        float4 v3 = __ldg(mb + (size_t)s3 * (LDC / 4) + lane);
        a0.x += v0.x; a0.y += v0.y; a0.z += v0.z; a0.w += v0.w;
        a1.x += v1.x; a1.y += v1.y; a1.z += v1.z; a1.w += v1.w;
        a0.x += v2.x; a0.y += v2.y; a0.z += v2.z; a0.w += v2.w;
        a1.x += v3.x; a1.y += v3.y; a1.z += v3.z; a1.w += v3.w;
    }
    for (; j < end; j++) {
        int s = __ldg(edge_src + j);
        float4 v = __ldg(mb + (size_t)s * (LDC / 4) + lane);
        a0.x += v.x; a0.y += v.y; a0.z += v.z; a0.w += v.w;
    }

    float4 r;
    r.x = a0.x + a1.x; r.y = a0.y + a1.y; r.z = a0.z + a1.z; r.w = a0.w + a1.w;
    *(reinterpret_cast<float4*>(agg) + (size_t)w * (LDC / 4) + lane) = r;
}

// ---------------------------------------------------------------------------
// Launch
// ---------------------------------------------------------------------------
extern "C" void kernel_launch(void* const* d_in, const int* in_sizes, int n_in,
                              void* d_out, int out_size)
{
    const float* features = (const float*)d_in[0];
    const int*   src      = (const int*)  d_in[1];
    const int*   dst      = (const int*)  d_in[2];
    const float* W1       = (const float*)d_in[3];
    const float* b1       = (const float*)d_in[4];
    const float* W2       = (const float*)d_in[5];
    const float* b2       = (const float*)d_in[6];
    float*       out      = (float*)d_out;

    const int M = in_sizes[0] / 128;   // 50000 nodes
    const int E = in_sizes[1];         // 800000 edges

    float *feat1;
    uint32_t *B1hi, *B1lo, *B2hi, *B2lo;
    int *cnt, *row_start, *cursor, *edge_src, *bsum, *boff;
    cudaGetSymbolAddress((void**)&feat1,     g_feat1);
    cudaGetSymbolAddress((void**)&cnt,       g_cnt);
    cudaGetSymbolAddress((void**)&row_start, g_row_start);
    cudaGetSymbolAddress((void**)&cursor,    g_cursor);
    cudaGetSymbolAddress((void**)&edge_src,  g_edge_src);
    cudaGetSymbolAddress((void**)&bsum,      g_bsum);
    cudaGetSymbolAddress((void**)&boff,      g_boff);
    cudaGetSymbolAddress((void**)&B1hi,      g_B1hi);
    cudaGetSymbolAddress((void**)&B1lo,      g_B1lo);
    cudaGetSymbolAddress((void**)&B2hi,      g_B2hi);
    cudaGetSymbolAddress((void**)&B2lo,      g_B2lo);

    cudaFuncSetAttribute(gemm_tc, cudaFuncAttributeMaxDynamicSharedMemorySize,
                         GEMM_SMEM_BYTES);

    const int gemm_blocks   = (M + 127) / 128;        // 391
    const int edge_blocks   = (E + 255) / 256;
    const int gather_blocks = (M + 7) / 8;
    const int scan_blocks   = (M + SCAN_B - 1) / SCAN_B;   // 196

    // --- W split/transpose (tiny) ---
    split_w_kernel<<<(128 * 128 + 255) / 256, 256>>>(W1, B1hi, B1lo, 128);
    split_w_kernel<<<(256 * 128 + 255) / 256, 256>>>(W2, B2hi, B2lo, 256);

    // --- CSR build (edges shared by both layers) ---
    cudaMemsetAsync(cnt, 0, (size_t)(M + 1) * sizeof(int));
    hist_kernel<<<edge_blocks, 256>>>(dst, cnt, E);
    reduce_kernel<<<scan_blocks, SCAN_B>>>(cnt, bsum, M);
    scan_sums_kernel<<<1, SCAN_B>>>(bsum, boff, scan_blocks);
    downsweep_kernel<<<scan_blocks, SCAN_B>>>(cnt, boff, row_start, cursor, M);
    fill_kernel<<<edge_blocks, 256>>>(src, dst, cursor, edge_src, E);

    // --- Layer 1 ---
    gemm_tc<<<gemm_blocks, 256, GEMM_SMEM_BYTES>>>(features, 128, B1hi, B1lo,
                                                   b1, feat1, M, 128);
    gather_kernel<<<gather_blocks, 256>>>(feat1 + 128, feat1, row_start, edge_src, M);

    // --- Layer 2 ---
    gemm_tc<<<gemm_blocks, 256, GEMM_SMEM_BYTES>>>(feat1, 256, B2hi, B2lo,
                                                   b2, out, M, 256);
    gather_kernel<<<gather_blocks, 256>>>(out + 128, out, row_start, edge_src, M);
}

// round 8
// speedup vs baseline: 2.2265x; 1.4109x over previous
#include <cuda_runtime.h>
#include <cuda_bf16.h>
#include <cstdint>

// ---------------------------------------------------------------------------
// GNN_85366769975686  (R7: 3x-bf16-split m16n8k16 GEMM + parallel CSR + gather)
//   layer(feat, W, b): m = feat@W + b ; agg = segment_sum(m[src], dst)
//                      return concat([agg, m], -1)
// N = 50000 nodes, E = 800000 edges, D = 128, output [N, 256] fp32.
// tcgen05 unusable (harness emits compute_103 PTX); tensor via sm_80 mma.sync.
// ---------------------------------------------------------------------------

#define N_MAX     50048
#define E_MAX     800000
#define LDC       256            // row stride (floats) of concat buffers
#define SCAN_B    256
#define SCAN_GRID ((N_MAX + SCAN_B - 1) / SCAN_B)   // 196

// Scratch (static — no allocations allowed)
__device__ float g_feat1[(size_t)N_MAX * LDC];
__device__ int   g_cnt[N_MAX + 1];
__device__ int   g_row_start[N_MAX + 1];
__device__ int   g_cursor[N_MAX + 1];
__device__ int   g_edge_src[E_MAX];
__device__ int   g_bsum[SCAN_GRID];
__device__ int   g_boff[SCAN_GRID];
// W split into bf16 hi/lo, packed bf16x2 along K, layout [n=128][K/2 words]
__device__ uint32_t g_B1hi[128 * 64];
__device__ uint32_t g_B1lo[128 * 64];
__device__ uint32_t g_B2hi[128 * 128];
__device__ uint32_t g_B2lo[128 * 128];

// ---------------------------------------------------------------------------
// helpers
// ---------------------------------------------------------------------------
__device__ __forceinline__ uint32_t pack_bf16x2(__nv_bfloat16 lo, __nv_bfloat16 hi) {
    __nv_bfloat162 t = __halves2bfloat162(lo, hi);   // .x = lo half
    return *reinterpret_cast<uint32_t*>(&t);
}

__device__ __forceinline__ void mma_bf16(float* d, const uint32_t* a,
                                         const uint32_t b0, const uint32_t b1) {
    asm volatile(
        "mma.sync.aligned.m16n8k16.row.col.f32.bf16.bf16.f32 "
        "{%0,%1,%2,%3}, {%4,%5,%6,%7}, {%8,%9}, {%0,%1,%2,%3};"
        : "+f"(d[0]), "+f"(d[1]), "+f"(d[2]), "+f"(d[3])
        : "r"(a[0]), "r"(a[1]), "r"(a[2]), "r"(a[3]), "r"(b0), "r"(b1));
}

// ---------------------------------------------------------------------------
// Prep: split W1[128,128] and W2[256,128] into bf16 hi/lo, packed [n][K/2]
// ---------------------------------------------------------------------------
__global__ void split_w_all(const float* __restrict__ W1,
                            uint32_t* __restrict__ B1hi, uint32_t* __restrict__ B1lo,
                            const float* __restrict__ W2,
                            uint32_t* __restrict__ B2hi, uint32_t* __restrict__ B2lo)
{
    int i = blockIdx.x * blockDim.x + threadIdx.x;
    const float* W; uint32_t *Bh, *Bl; int K, j;
    if (i < 128 * 64) { W = W1; Bh = B1hi; Bl = B1lo; K = 128; j = i; }
    else if (i < 128 * 64 + 128 * 128) {
        W = W2; Bh = B2hi; Bl = B2lo; K = 256; j = i - 128 * 64;
    } else return;

    int kp = j >> 7;        // k-pair index
    int n  = j & 127;
    float w0 = W[(2 * kp) * 128 + n];
    float w1 = W[(2 * kp + 1) * 128 + n];
    __nv_bfloat16 h0 = __float2bfloat16_rn(w0);
    __nv_bfloat16 h1 = __float2bfloat16_rn(w1);
    __nv_bfloat16 l0 = __float2bfloat16_rn(w0 - __bfloat162float(h0));
    __nv_bfloat16 l1 = __float2bfloat16_rn(w1 - __bfloat162float(h1));
    Bh[n * (K >> 1) + kp] = pack_bf16x2(h0, h1);
    Bl[n * (K >> 1) + kp] = pack_bf16x2(l0, l1);
}

// ---------------------------------------------------------------------------
// 3x-bf16 mma.sync GEMM: C[row, 128+col] = sum_k A[row,k]*W[k,col] + bias[col]
// CTA: 256 threads, tile 128(M) x 128(N), K-chunk 32 elements (16 words).
// Warps: 4(M) x 2(N); warp tile 32 x 64; mma m16n8k16.
// Row pad 20 words: fragment LDS bank = (g*20 + tg) % 32 — conflict-free.
// ---------------------------------------------------------------------------
#define APAD 20
#define SM_AHI 0
#define SM_ALO (128 * APAD)
#define SM_BHI (2 * 128 * APAD)
#define SM_BLO (3 * 128 * APAD)

__global__ __launch_bounds__(256)
void gemm_tc(const float* __restrict__ A, int lda,
             const uint32_t* __restrict__ Bhi, const uint32_t* __restrict__ Blo,
             const float* __restrict__ bias,
             float* __restrict__ C, int M, int K)
{
    __shared__ uint32_t sm[4 * 128 * APAD];   // 40 KB

    const int tid  = threadIdx.x;
    const int wid  = tid >> 5;
    const int lane = tid & 31;
    const int g    = lane >> 2;
    const int tg   = lane & 3;
    const int wm   = wid & 3;
    const int wn   = wid >> 2;
    const int row0 = blockIdx.x * 128;
    const int Kw   = K >> 1;                  // words per B row

    float d[2][8][4];
#pragma unroll
    for (int i = 0; i < 2; i++)
#pragma unroll
        for (int j = 0; j < 8; j++)
#pragma unroll
            for (int c = 0; c < 4; c++) d[i][j][c] = 0.0f;

    const int nch = K >> 5;
    for (int kc = 0; kc < nch; kc++) {
        // ---- stage chunk: A fp32->bf16 hi/lo split, B hi/lo copy ----
#pragma unroll
        for (int l = 0; l < 4; l++) {
            int idx = tid + l * 256;     // 1024 float4 slots
            int row = idx >> 3;          // 0..127
            int c4  = idx & 7;           // float4 within 32-float chunk row
            int wo  = row * APAD + c4 * 2;

            int gr = row0 + row;
            float4 v = make_float4(0.f, 0.f, 0.f, 0.f);
            if (gr < M)
                v = *reinterpret_cast<const float4*>(A + (size_t)gr * lda + kc * 32 + c4 * 4);
            __nv_bfloat16 hx = __float2bfloat16_rn(v.x);
            __nv_bfloat16 hy = __float2bfloat16_rn(v.y);
            __nv_bfloat16 hz = __float2bfloat16_rn(v.z);
            __nv_bfloat16 hw = __float2bfloat16_rn(v.w);
            uint2 hv, lv;
            hv.x = pack_bf16x2(hx, hy);
            hv.y = pack_bf16x2(hz, hw);
            lv.x = pack_bf16x2(__float2bfloat16_rn(v.x - __bfloat162float(hx)),
                               __float2bfloat16_rn(v.y - __bfloat162float(hy)));
            lv.y = pack_bf16x2(__float2bfloat16_rn(v.z - __bfloat162float(hz)),
                               __float2bfloat16_rn(v.w - __bfloat162float(hw)));
            *reinterpret_cast<uint2*>(sm + SM_AHI + wo) = hv;
            *reinterpret_cast<uint2*>(sm + SM_ALO + wo) = lv;

            const size_t bofs = (size_t)row * Kw + kc * 16 + c4 * 2;
            *reinterpret_cast<uint2*>(sm + SM_BHI + wo) =
                *reinterpret_cast<const uint2*>(Bhi + bofs);
            *reinterpret_cast<uint2*>(sm + SM_BLO + wo) =
                *reinterpret_cast<const uint2*>(Blo + bofs);
        }
        __syncthreads();

        // ---- compute: 2 k16 steps ----
#pragma unroll
        for (int ks = 0; ks < 2; ks++) {
            const int kk = ks * 8;       // word offset of this k16 step
            uint32_t ah[2][4], al[2][4];
#pragma unroll
            for (int mf = 0; mf < 2; mf++) {
                int r0 = (wm * 32 + mf * 16 + g) * APAD + kk + tg;
                int r8 = r0 + 8 * APAD;
                ah[mf][0] = sm[SM_AHI + r0];
                ah[mf][1] = sm[SM_AHI + r8];
                ah[mf][2] = sm[SM_AHI + r0 + 4];
                ah[mf][3] = sm[SM_AHI + r8 + 4];
                al[mf][0] = sm[SM_ALO + r0];
                al[mf][1] = sm[SM_ALO + r8];
                al[mf][2] = sm[SM_ALO + r0 + 4];
                al[mf][3] = sm[SM_ALO + r8 + 4];
            }
#pragma unroll
            for (int nf = 0; nf < 8; nf++) {
                int bo = (wn * 64 + nf * 8 + g) * APAD + kk + tg;
                uint32_t bh0 = sm[SM_BHI + bo];
                uint32_t bh1 = sm[SM_BHI + bo + 4];
                uint32_t bl0 = sm[SM_BLO + bo];
                uint32_t bl1 = sm[SM_BLO + bo + 4];
#pragma unroll
                for (int mf = 0; mf < 2; mf++) {
                    mma_bf16(d[mf][nf], ah[mf], bh0, bh1);
                    mma_bf16(d[mf][nf], al[mf], bh0, bh1);
                    mma_bf16(d[mf][nf], ah[mf], bl0, bl1);
                }
            }
        }
        __syncthreads();
    }

    // ---- epilogue: + bias, write C[:, 128..256) ----
#pragma unroll
    for (int nf = 0; nf < 8; nf++) {
        const int col = wn * 64 + nf * 8 + tg * 2;
        const float b0 = __ldg(bias + col);
        const float b1 = __ldg(bias + col + 1);
#pragma unroll
        for (int mf = 0; mf < 2; mf++) {
            int r = row0 + wm * 32 + mf * 16 + g;
            if (r < M) {
                float2 v0 = make_float2(d[mf][nf][0] + b0, d[mf][nf][1] + b1);
                *reinterpret_cast<float2*>(C + (size_t)r * LDC + 128 + col) = v0;
            }
            if (r + 8 < M) {
                float2 v1 = make_float2(d[mf][nf][2] + b0, d[mf][nf][3] + b1);
                *reinterpret_cast<float2*>(C + (size_t)(r + 8) * LDC + 128 + col) = v1;
            }
        }
    }
}

// ---------------------------------------------------------------------------
// CSR build: histogram
// ---------------------------------------------------------------------------
__global__ void hist_kernel(const int* __restrict__ dst, int* __restrict__ cnt, int E)
{
    int e = blockIdx.x * blockDim.x + threadIdx.x;
    if (e < E) atomicAdd(&cnt[__ldg(dst + e)], 1);
}

// ---------------------------------------------------------------------------
// Parallel exclusive scan (3 phases)
// ---------------------------------------------------------------------------
__global__ __launch_bounds__(SCAN_B)
void reduce_kernel(const int* __restrict__ cnt, int* __restrict__ bsum, int n)
{
    __shared__ int ws[8];
    const int tid = threadIdx.x;
    const int i   = blockIdx.x * SCAN_B + tid;
    int v = (i < n) ? cnt[i] : 0;
#pragma unroll
    for (int o = 16; o > 0; o >>= 1) v += __shfl_down_sync(0xffffffffu, v, o);
    if ((tid & 31) == 0) ws[tid >> 5] = v;
    __syncthreads();
    if (tid < 8) {
        int s = ws[tid];
#pragma unroll
        for (int o = 4; o > 0; o >>= 1) s += __shfl_down_sync(0xffu, s, o);
        if (tid == 0) bsum[blockIdx.x] = s;
    }
}

__global__ __launch_bounds__(SCAN_B)
void scan_sums_kernel(const int* __restrict__ bsum, int* __restrict__ boff, int nb)
{
    __shared__ int ws[8];
    const int tid  = threadIdx.x;
    const int lane = tid & 31;
    const int w    = tid >> 5;
    int c = (tid < nb) ? bsum[tid] : 0;
    int v = c;
#pragma unroll
    for (int o = 1; o < 32; o <<= 1) {
        int u = __shfl_up_sync(0xffffffffu, v, o);
        if (lane >= o) v += u;
    }
    if (lane == 31) ws[w] = v;
    __syncthreads();
    if (tid < 8) {
        int s = ws[tid];
        int t = s;
#pragma unroll
        for (int o = 1; o < 8; o <<= 1) {
            int u = __shfl_up_sync(0xffu, t, o);
            if (tid >= o) t += u;
        }
        ws[tid] = t - s;
    }
    __syncthreads();
    if (tid < nb) boff[tid] = v - c + ws[w];
}

__global__ __launch_bounds__(SCAN_B)
void downsweep_kernel(const int* __restrict__ cnt, const int* __restrict__ boff,
                      int* __restrict__ row_start, int* __restrict__ cursor, int n)
{
    __shared__ int ws[8];
    const int tid  = threadIdx.x;
    const int lane = tid & 31;
    const int w    = tid >> 5;
    const int i    = blockIdx.x * SCAN_B + tid;
    int c = (i < n) ? cnt[i] : 0;
    int v = c;
#pragma unroll
    for (int o = 1; o < 32; o <<= 1) {
        int u = __shfl_up_sync(0xffffffffu, v, o);
        if (lane >= o) v += u;
    }
    if (lane == 31) ws[w] = v;
    __syncthreads();
    if (tid < 8) {
        int s = ws[tid];
        int t = s;
#pragma unroll
        for (int o = 1; o < 8; o <<= 1) {
            int u = __shfl_up_sync(0xffu, t, o);
            if (tid >= o) t += u;
        }
        ws[tid] = t - s;
    }
    __syncthreads();
    if (i < n) {
        int ex = boff[blockIdx.x] + ws[w] + v - c;
        row_start[i] = ex;
        cursor[i]    = ex;
        if (i == n - 1) row_start[n] = ex + c;
    }
}

// ---------------------------------------------------------------------------
// CSR build: fill buckets
// ---------------------------------------------------------------------------
__global__ void fill_kernel(const int* __restrict__ src, const int* __restrict__ dst,
                            int* __restrict__ cursor, int* __restrict__ edge_src, int E)
{
    int e = blockIdx.x * blockDim.x + threadIdx.x;
    if (e < E) {
        int p = atomicAdd(&cursor[__ldg(dst + e)], 1);
        edge_src[p] = __ldg(src + e);
    }
}

// ---------------------------------------------------------------------------
// Aggregation: one warp per destination node (register accumulation, 1 store)
// ---------------------------------------------------------------------------
__global__ __launch_bounds__(256)
void gather_kernel(const float* __restrict__ msg,
                   float* __restrict__ agg,
                   const int* __restrict__ row_start,
                   const int* __restrict__ edge_src,
                   int n)
{
    int w    = (blockIdx.x * blockDim.x + threadIdx.x) >> 5;
    int lane = threadIdx.x & 31;
    if (w >= n) return;

    const int start = __ldg(row_start + w);
    const int end   = __ldg(row_start + w + 1);

    const float4* mb = reinterpret_cast<const float4*>(msg);
    float4 a0 = make_float4(0.f, 0.f, 0.f, 0.f);
    float4 a1 = make_float4(0.f, 0.f, 0.f, 0.f);

    int j = start;
    for (; j + 4 <= end; j += 4) {
        int s0 = __ldg(edge_src + j);
        int s1 = __ldg(edge_src + j + 1);
        int s2 = __ldg(edge_src + j + 2);
        int s3 = __ldg(edge_src + j + 3);
        float4 v0 = __ldg(mb + (size_t)s0 * (LDC / 4) + lane);
        float4 v1 = __ldg(mb + (size_t)s1 * (LDC / 4) + lane);
        float4 v2 = __ldg(mb + (size_t)s2 * (LDC / 4) + lane);
        float4 v3 = __ldg(mb + (size_t)s3 * (LDC / 4) + lane);
        a0.x += v0.x; a0.y += v0.y; a0.z += v0.z; a0.w += v0.w;
        a1.x += v1.x; a1.y += v1.y; a1.z += v1.z; a1.w += v1.w;
        a0.x += v2.x; a0.y += v2.y; a0.z += v2.z; a0.w += v2.w;
        a1.x += v3.x; a1.y += v3.y; a1.z += v3.z; a1.w += v3.w;
    }
    for (; j < end; j++) {
        int s = __ldg(edge_src + j);
        float4 v = __ldg(mb + (size_t)s * (LDC / 4) + lane);
        a0.x += v.x; a0.y += v.y; a0.z += v.z; a0.w += v.w;
    }

    float4 r;
    r.x = a0.x + a1.x; r.y = a0.y + a1.y; r.z = a0.z + a1.z; r.w = a0.w + a1.w;
    *(reinterpret_cast<float4*>(agg) + (size_t)w * (LDC / 4) + lane) = r;
}

// ---------------------------------------------------------------------------
// Launch
// ---------------------------------------------------------------------------
extern "C" void kernel_launch(void* const* d_in, const int* in_sizes, int n_in,
                              void* d_out, int out_size)
{
    const float* features = (const float*)d_in[0];
    const int*   src      = (const int*)  d_in[1];
    const int*   dst      = (const int*)  d_in[2];
    const float* W1       = (const float*)d_in[3];
    const float* b1       = (const float*)d_in[4];
    const float* W2       = (const float*)d_in[5];
    const float* b2       = (const float*)d_in[6];
    float*       out      = (float*)d_out;

    const int M = in_sizes[0] / 128;   // 50000 nodes
    const int E = in_sizes[1];         // 800000 edges

    float *feat1;
    uint32_t *B1hi, *B1lo, *B2hi, *B2lo;
    int *cnt, *row_start, *cursor, *edge_src, *bsum, *boff;
    cudaGetSymbolAddress((void**)&feat1,     g_feat1);
    cudaGetSymbolAddress((void**)&cnt,       g_cnt);
    cudaGetSymbolAddress((void**)&row_start, g_row_start);
    cudaGetSymbolAddress((void**)&cursor,    g_cursor);
    cudaGetSymbolAddress((void**)&edge_src,  g_edge_src);
    cudaGetSymbolAddress((void**)&bsum,      g_bsum);
    cudaGetSymbolAddress((void**)&boff,      g_boff);
    cudaGetSymbolAddress((void**)&B1hi,      g_B1hi);
    cudaGetSymbolAddress((void**)&B1lo,      g_B1lo);
    cudaGetSymbolAddress((void**)&B2hi,      g_B2hi);
    cudaGetSymbolAddress((void**)&B2lo,      g_B2lo);

    const int gemm_blocks   = (M + 127) / 128;             // 391
    const int edge_blocks   = (E + 255) / 256;
    const int gather_blocks = (M + 7) / 8;
    const int scan_blocks   = (M + SCAN_B - 1) / SCAN_B;   // 196
    const int split_threads = 128 * 64 + 128 * 128;        // 24576

    // --- W split (single launch) ---
    split_w_all<<<(split_threads + 255) / 256, 256>>>(W1, B1hi, B1lo, W2, B2hi, B2lo);

    // --- CSR build (edges shared by both layers) ---
    cudaMemsetAsync(cnt, 0, (size_t)(M + 1) * sizeof(int));
    hist_kernel<<<edge_blocks, 256>>>(dst, cnt, E);
    reduce_kernel<<<scan_blocks, SCAN_B>>>(cnt, bsum, M);
    scan_sums_kernel<<<1, SCAN_B>>>(bsum, boff, scan_blocks);
    downsweep_kernel<<<scan_blocks, SCAN_B>>>(cnt, boff, row_start, cursor, M);
    fill_kernel<<<edge_blocks, 256>>>(src, dst, cursor, edge_src, E);

    // --- Layer 1 ---
    gemm_tc<<<gemm_blocks, 256>>>(features, 128, B1hi, B1lo, b1, feat1, M, 128);
    gather_kernel<<<gather_blocks, 256>>>(feat1 + 128, feat1, row_start, edge_src, M);

    // --- Layer 2 ---
    gemm_tc<<<gemm_blocks, 256>>>(feat1, 256, B2hi, B2lo, b2, out, M, 256);
    gather_kernel<<<gather_blocks, 256>>>(out + 128, out, row_start, edge_src, M);
}

// round 9
// speedup vs baseline: 2.2797x; 1.0239x over previous
#include <cuda_runtime.h>
#include <cuda_bf16.h>
#include <cstdint>

// ---------------------------------------------------------------------------
// GNN_85366769975686  (R8: fused-DAG — prep+split, lookback scan, fill||GEMM1)
//   layer(feat, W, b): m = feat@W + b ; agg = segment_sum(m[src], dst)
//                      return concat([agg, m], -1)
// N = 50000 nodes, E = 800000 edges, D = 128, output [N, 256] fp32.
// tcgen05 unusable (harness emits compute_103 PTX); tensor via sm_80 mma.sync.
// GEMM: 3x-bf16-split m16n8k16 (D = Ah*Bh + Al*Bh + Ah*Bl), rel_err ~6e-6.
// ---------------------------------------------------------------------------

#define N_MAX     50048
#define E_MAX     800000
#define LDC       256            // row stride (floats) of concat buffers
#define SCAN_B    256
#define SCAN_GRID ((N_MAX + SCAN_B - 1) / SCAN_B)   // 196

// Scratch (static — no allocations allowed)
__device__ float g_feat1[(size_t)N_MAX * LDC];
__device__ int   g_cnt[N_MAX + 1];
__device__ int   g_row_start[N_MAX + 1];
__device__ int   g_cursor[N_MAX + 1];
__device__ int   g_edge_src[E_MAX];
__device__ unsigned long long g_scan_state[SCAN_GRID];  // (flag<<62)|value
// W split into bf16 hi/lo, packed bf16x2 along K, layout [n=128][K/2 words]
__device__ uint32_t g_B1hi[128 * 64];
__device__ uint32_t g_B1lo[128 * 64];
__device__ uint32_t g_B2hi[128 * 128];
__device__ uint32_t g_B2lo[128 * 128];

// ---------------------------------------------------------------------------
// helpers
// ---------------------------------------------------------------------------
__device__ __forceinline__ uint32_t pack_bf16x2(__nv_bfloat16 lo, __nv_bfloat16 hi) {
    __nv_bfloat162 t = __halves2bfloat162(lo, hi);   // .x = lo half
    return *reinterpret_cast<uint32_t*>(&t);
}

__device__ __forceinline__ void mma_bf16(float* d, const uint32_t* a,
                                         const uint32_t b0, const uint32_t b1) {
    asm volatile(
        "mma.sync.aligned.m16n8k16.row.col.f32.bf16.bf16.f32 "
        "{%0,%1,%2,%3}, {%4,%5,%6,%7}, {%8,%9}, {%0,%1,%2,%3};"
        : "+f"(d[0]), "+f"(d[1]), "+f"(d[2]), "+f"(d[3])
        : "r"(a[0]), "r"(a[1]), "r"(a[2]), "r"(a[3]), "r"(b0), "r"(b1));
}

// ---------------------------------------------------------------------------
// GEMM body (device fn): C[row, 128+col] = sum_k A[row,k]*W[k,col] + bias[col]
// Tile 128(M) x 128(N), K-chunk 32; warps 4(M)x2(N); mma m16n8k16.
// Row pad 20 words: fragment LDS bank = (g*20 + tg) % 32 — conflict-free.
// ---------------------------------------------------------------------------
#define APAD 20
#define SM_AHI 0
#define SM_ALO (128 * APAD)
#define SM_BHI (2 * 128 * APAD)
#define SM_BLO (3 * 128 * APAD)

__device__ __forceinline__
void gemm_body(int bx, const float* __restrict__ A, int lda,
               const uint32_t* __restrict__ Bhi, const uint32_t* __restrict__ Blo,
               const float* __restrict__ bias,
               float* __restrict__ C, int M, int K)
{
    __shared__ uint32_t sm[4 * 128 * APAD];   // 40 KB

    const int tid  = threadIdx.x;
    const int wid  = tid >> 5;
    const int lane = tid & 31;
    const int g    = lane >> 2;
    const int tg   = lane & 3;
    const int wm   = wid & 3;
    const int wn   = wid >> 2;
    const int row0 = bx * 128;
    const int Kw   = K >> 1;

    float d[2][8][4];
#pragma unroll
    for (int i = 0; i < 2; i++)
#pragma unroll
        for (int j = 0; j < 8; j++)
#pragma unroll
            for (int c = 0; c < 4; c++) d[i][j][c] = 0.0f;

    const int nch = K >> 5;
    for (int kc = 0; kc < nch; kc++) {
#pragma unroll
        for (int l = 0; l < 4; l++) {
            int idx = tid + l * 256;
            int row = idx >> 3;
            int c4  = idx & 7;
            int wo  = row * APAD + c4 * 2;

            int gr = row0 + row;
            float4 v = make_float4(0.f, 0.f, 0.f, 0.f);
            if (gr < M)
                v = *reinterpret_cast<const float4*>(A + (size_t)gr * lda + kc * 32 + c4 * 4);
            __nv_bfloat16 hx = __float2bfloat16_rn(v.x);
            __nv_bfloat16 hy = __float2bfloat16_rn(v.y);
            __nv_bfloat16 hz = __float2bfloat16_rn(v.z);
            __nv_bfloat16 hw = __float2bfloat16_rn(v.w);
            uint2 hv, lv;
            hv.x = pack_bf16x2(hx, hy);
            hv.y = pack_bf16x2(hz, hw);
            lv.x = pack_bf16x2(__float2bfloat16_rn(v.x - __bfloat162float(hx)),
                               __float2bfloat16_rn(v.y - __bfloat162float(hy)));
            lv.y = pack_bf16x2(__float2bfloat16_rn(v.z - __bfloat162float(hz)),
                               __float2bfloat16_rn(v.w - __bfloat162float(hw)));
            *reinterpret_cast<uint2*>(sm + SM_AHI + wo) = hv;
            *reinterpret_cast<uint2*>(sm + SM_ALO + wo) = lv;

            const size_t bofs = (size_t)row * Kw + kc * 16 + c4 * 2;
            *reinterpret_cast<uint2*>(sm + SM_BHI + wo) =
                *reinterpret_cast<const uint2*>(Bhi + bofs);
            *reinterpret_cast<uint2*>(sm + SM_BLO + wo) =
                *reinterpret_cast<const uint2*>(Blo + bofs);
        }
        __syncthreads();

#pragma unroll
        for (int ks = 0; ks < 2; ks++) {
            const int kk = ks * 8;
            uint32_t ah[2][4], al[2][4];
#pragma unroll
            for (int mf = 0; mf < 2; mf++) {
                int r0 = (wm * 32 + mf * 16 + g) * APAD + kk + tg;
                int r8 = r0 + 8 * APAD;
                ah[mf][0] = sm[SM_AHI + r0];
                ah[mf][1] = sm[SM_AHI + r8];
                ah[mf][2] = sm[SM_AHI + r0 + 4];
                ah[mf][3] = sm[SM_AHI + r8 + 4];
                al[mf][0] = sm[SM_ALO + r0];
                al[mf][1] = sm[SM_ALO + r8];
                al[mf][2] = sm[SM_ALO + r0 + 4];
                al[mf][3] = sm[SM_ALO + r8 + 4];
            }
#pragma unroll
            for (int nf = 0; nf < 8; nf++) {
                int bo = (wn * 64 + nf * 8 + g) * APAD + kk + tg;
                uint32_t bh0 = sm[SM_BHI + bo];
                uint32_t bh1 = sm[SM_BHI + bo + 4];
                uint32_t bl0 = sm[SM_BLO + bo];
                uint32_t bl1 = sm[SM_BLO + bo + 4];
#pragma unroll
                for (int mf = 0; mf < 2; mf++) {
                    mma_bf16(d[mf][nf], ah[mf], bh0, bh1);
                    mma_bf16(d[mf][nf], al[mf], bh0, bh1);
                    mma_bf16(d[mf][nf], ah[mf], bl0, bl1);
                }
            }
        }
        __syncthreads();
    }

#pragma unroll
    for (int nf = 0; nf < 8; nf++) {
        const int col = wn * 64 + nf * 8 + tg * 2;
        const float b0 = __ldg(bias + col);
        const float b1 = __ldg(bias + col + 1);
#pragma unroll
        for (int mf = 0; mf < 2; mf++) {
            int r = row0 + wm * 32 + mf * 16 + g;
            if (r < M) {
                float2 v0 = make_float2(d[mf][nf][0] + b0, d[mf][nf][1] + b1);
                *reinterpret_cast<float2*>(C + (size_t)r * LDC + 128 + col) = v0;
            }
            if (r + 8 < M) {
                float2 v1 = make_float2(d[mf][nf][2] + b0, d[mf][nf][3] + b1);
                *reinterpret_cast<float2*>(C + (size_t)(r + 8) * LDC + 128 + col) = v1;
            }
        }
    }
}

__global__ __launch_bounds__(256)
void gemm_tc(const float* __restrict__ A, int lda,
             const uint32_t* __restrict__ Bhi, const uint32_t* __restrict__ Blo,
             const float* __restrict__ bias,
             float* __restrict__ C, int M, int K)
{
    gemm_body(blockIdx.x, A, lda, Bhi, Blo, bias, C, M, K);
}

// ---------------------------------------------------------------------------
// L1 prep: split W1/W2 into bf16 hi/lo  +  zero cnt and scan states
// Blocks [0, 96): split (24576 threads). Blocks [96, 96+196): zeroing.
// ---------------------------------------------------------------------------
#define SPLIT_BLOCKS 96
#define ZERO_BLOCKS  196

__global__ __launch_bounds__(256)
void prep_kernel(const float* __restrict__ W1,
                 uint32_t* __restrict__ B1hi, uint32_t* __restrict__ B1lo,
                 const float* __restrict__ W2,
                 uint32_t* __restrict__ B2hi, uint32_t* __restrict__ B2lo,
                 int* __restrict__ cnt, unsigned long long* __restrict__ state,
                 int n)
{
    const int b = blockIdx.x;
    if (b < SPLIT_BLOCKS) {
        int i = b * 256 + threadIdx.x;   // 0 .. 24575
        const float* W; uint32_t *Bh, *Bl; int K, j;
        if (i < 128 * 64) { W = W1; Bh = B1hi; Bl = B1lo; K = 128; j = i; }
        else { W = W2; Bh = B2hi; Bl = B2lo; K = 256; j = i - 128 * 64; }
        int kp = j >> 7;
        int nn = j & 127;
        float w0 = W[(2 * kp) * 128 + nn];
        float w1 = W[(2 * kp + 1) * 128 + nn];
        __nv_bfloat16 h0 = __float2bfloat16_rn(w0);
        __nv_bfloat16 h1 = __float2bfloat16_rn(w1);
        __nv_bfloat16 l0 = __float2bfloat16_rn(w0 - __bfloat162float(h0));
        __nv_bfloat16 l1 = __float2bfloat16_rn(w1 - __bfloat162float(h1));
        Bh[nn * (K >> 1) + kp] = pack_bf16x2(h0, h1);
        Bl[nn * (K >> 1) + kp] = pack_bf16x2(l0, l1);
    } else {
        int i = (b - SPLIT_BLOCKS) * 256 + threadIdx.x;
        if (i <= n) cnt[i] = 0;
        if (i < SCAN_GRID) state[i] = 0ULL;
    }
}

// ---------------------------------------------------------------------------
// CSR: histogram of dst
// ---------------------------------------------------------------------------
__global__ void hist_kernel(const int* __restrict__ dst, int* __restrict__ cnt, int E)
{
    int e = blockIdx.x * blockDim.x + threadIdx.x;
    if (e < E) atomicAdd(&cnt[__ldg(dst + e)], 1);
}

// ---------------------------------------------------------------------------
// Single-pass exclusive scan with decoupled lookback.
// 196 blocks x 256 threads; all blocks co-resident (no deadlock possible).
// state[b] = (flag << 62) | value; flag 1 = aggregate, 2 = inclusive prefix.
// ---------------------------------------------------------------------------
__global__ __launch_bounds__(SCAN_B)
void scan_lookback_kernel(const int* __restrict__ cnt,
                          int* __restrict__ row_start, int* __restrict__ cursor,
                          unsigned long long* __restrict__ state, int n)
{
    __shared__ int ws[8];
    __shared__ int s_prefix;
    const int b    = blockIdx.x;
    const int tid  = threadIdx.x;
    const int lane = tid & 31;
    const int w    = tid >> 5;
    const int i    = b * SCAN_B + tid;

    int c = (i < n) ? cnt[i] : 0;
    int v = c;
#pragma unroll
    for (int o = 1; o < 32; o <<= 1) {
        int u = __shfl_up_sync(0xffffffffu, v, o);
        if (lane >= o) v += u;
    }
    if (lane == 31) ws[w] = v;
    __syncthreads();
    if (tid < 8) {
        int s = ws[tid];
        int t = s;
#pragma unroll
        for (int o = 1; o < 8; o <<= 1) {
            int u = __shfl_up_sync(0xffu, t, o);
            if (tid >= o) t += u;
        }
        ws[tid] = t - s;                 // exclusive warp offset
        if (tid == 7) s_prefix = t;      // stash block total temporarily
    }
    __syncthreads();
    const int local_ex = ws[w] + v - c;  // block-local exclusive prefix
    const int total    = s_prefix;       // block total (all counts in block)

    if (tid == 0) {
        int prefix = 0;
        if (b == 0) {
            atomicExch(&state[0], (2ULL << 62) | (unsigned int)total);
        } else {
            atomicExch(&state[b], (1ULL << 62) | (unsigned int)total);
            int p = b - 1;
            for (;;) {
                unsigned long long s;
                do { s = atomicAdd(&state[p], 0ULL); } while ((s >> 62) == 0ULL);
                prefix += (int)(s & 0xffffffffULL);
                if ((s >> 62) == 2ULL) break;
                p--;
            }
            atomicExch(&state[b], (2ULL << 62) | (unsigned int)(prefix + total));
        }
        s_prefix = prefix;
    }
    __syncthreads();

    if (i < n) {
        int ex = s_prefix + local_ex;
        row_start[i] = ex;
        cursor[i]    = ex;
        if (i == n - 1) row_start[n] = ex + c;
    }
}

// ---------------------------------------------------------------------------
// Fused launch: blocks [0, gemm_blocks) run GEMM1; the rest fill CSR buckets.
// fill: 4 edges per thread (independent -> pipelined atomics).
// ---------------------------------------------------------------------------
__global__ __launch_bounds__(256)
void fill_gemm1_kernel(const int* __restrict__ src, const int* __restrict__ dst,
                       int* __restrict__ cursor, int* __restrict__ edge_src, int E,
                       int gemm_blocks,
                       const float* __restrict__ A,
                       const uint32_t* __restrict__ Bhi, const uint32_t* __restrict__ Blo,
                       const float* __restrict__ bias,
                       float* __restrict__ C, int M)
{
    if ((int)blockIdx.x < gemm_blocks) {
        gemm_body(blockIdx.x, A, 128, Bhi, Blo, bias, C, M, 128);
    } else {
        int base = (blockIdx.x - gemm_blocks) * 1024 + threadIdx.x;
#pragma unroll
        for (int u = 0; u < 4; u++) {
            int e = base + u * 256;
            if (e < E) {
                int p = atomicAdd(&cursor[__ldg(dst + e)], 1);
                edge_src[p] = __ldg(src + e);
            }
        }
    }
}

// ---------------------------------------------------------------------------
// Aggregation: one warp per destination node (register accumulation, 1 store)
// ---------------------------------------------------------------------------
__global__ __launch_bounds__(256)
void gather_kernel(const float* __restrict__ msg,
                   float* __restrict__ agg,
                   const int* __restrict__ row_start,
                   const int* __restrict__ edge_src,
                   int n)
{
    int w    = (blockIdx.x * blockDim.x + threadIdx.x) >> 5;
    int lane = threadIdx.x & 31;
    if (w >= n) return;

    const int start = __ldg(row_start + w);
    const int end   = __ldg(row_start + w + 1);

    const float4* mb = reinterpret_cast<const float4*>(msg);
    float4 a0 = make_float4(0.f, 0.f, 0.f, 0.f);
    float4 a1 = make_float4(0.f, 0.f, 0.f, 0.f);

    int j = start;
    for (; j + 4 <= end; j += 4) {
        int s0 = __ldg(edge_src + j);
        int s1 = __ldg(edge_src + j + 1);
        int s2 = __ldg(edge_src + j + 2);
        int s3 = __ldg(edge_src + j + 3);
        float4 v0 = __ldg(mb + (size_t)s0 * (LDC / 4) + lane);
        float4 v1 = __ldg(mb + (size_t)s1 * (LDC / 4) + lane);
        float4 v2 = __ldg(mb + (size_t)s2 * (LDC / 4) + lane);
        float4 v3 = __ldg(mb + (size_t)s3 * (LDC / 4) + lane);
        a0.x += v0.x; a0.y += v0.y; a0.z += v0.z; a0.w += v0.w;
        a1.x += v1.x; a1.y += v1.y; a1.z += v1.z; a1.w += v1.w;
        a0.x += v2.x; a0.y += v2.y; a0.z += v2.z; a0.w += v2.w;
        a1.x += v3.x; a1.y += v3.y; a1.z += v3.z; a1.w += v3.w;
    }
    for (; j < end; j++) {
        int s = __ldg(edge_src + j);
        float4 v = __ldg(mb + (size_t)s * (LDC / 4) + lane);
        a0.x += v.x; a0.y += v.y; a0.z += v.z; a0.w += v.w;
    }

    float4 r;
    r.x = a0.x + a1.x; r.y = a0.y + a1.y; r.z = a0.z + a1.z; r.w = a0.w + a1.w;
    *(reinterpret_cast<float4*>(agg) + (size_t)w * (LDC / 4) + lane) = r;
}

// ---------------------------------------------------------------------------
// Launch (7 graph nodes)
// ---------------------------------------------------------------------------
extern "C" void kernel_launch(void* const* d_in, const int* in_sizes, int n_in,
                              void* d_out, int out_size)
{
    const float* features = (const float*)d_in[0];
    const int*   src      = (const int*)  d_in[1];
    const int*   dst      = (const int*)  d_in[2];
    const float* W1       = (const float*)d_in[3];
    const float* b1       = (const float*)d_in[4];
    const float* W2       = (const float*)d_in[5];
    const float* b2       = (const float*)d_in[6];
    float*       out      = (float*)d_out;

    const int M = in_sizes[0] / 128;   // 50000 nodes
    const int E = in_sizes[1];         // 800000 edges

    float *feat1;
    uint32_t *B1hi, *B1lo, *B2hi, *B2lo;
    int *cnt, *row_start, *cursor, *edge_src;
    unsigned long long *state;
    cudaGetSymbolAddress((void**)&feat1,     g_feat1);
    cudaGetSymbolAddress((void**)&cnt,       g_cnt);
    cudaGetSymbolAddress((void**)&row_start, g_row_start);
    cudaGetSymbolAddress((void**)&cursor,    g_cursor);
    cudaGetSymbolAddress((void**)&edge_src,  g_edge_src);
    cudaGetSymbolAddress((void**)&state,     g_scan_state);
    cudaGetSymbolAddress((void**)&B1hi,      g_B1hi);
    cudaGetSymbolAddress((void**)&B1lo,      g_B1lo);
    cudaGetSymbolAddress((void**)&B2hi,      g_B2hi);
    cudaGetSymbolAddress((void**)&B2lo,      g_B2lo);

    const int gemm_blocks   = (M + 127) / 128;              // 391
    const int edge_blocks   = (E + 255) / 256;              // 3125
    const int fill_blocks   = (E + 1023) / 1024;            // 782
    const int gather_blocks = (M + 7) / 8;                  // 6250
    const int scan_blocks   = (M + SCAN_B - 1) / SCAN_B;    // 196

    // L1: W split + zero cnt/scan-state
    prep_kernel<<<SPLIT_BLOCKS + ZERO_BLOCKS, 256>>>(W1, B1hi, B1lo, W2, B2hi, B2lo,
                                                     cnt, state, M);
    // L2: degree histogram
    hist_kernel<<<edge_blocks, 256>>>(dst, cnt, E);
    // L3: single-pass scan (row_start + cursor)
    scan_lookback_kernel<<<scan_blocks, SCAN_B>>>(cnt, row_start, cursor, state, M);
    // L4: CSR bucket fill  ||  GEMM1 (independent, one launch)
    fill_gemm1_kernel<<<gemm_blocks + fill_blocks, 256>>>(src, dst, cursor, edge_src, E,
                                                          gemm_blocks,
                                                          features, B1hi, B1lo, b1,
                                                          feat1, M);
    // L5: gather layer 1
    gather_kernel<<<gather_blocks, 256>>>(feat1 + 128, feat1, row_start, edge_src, M);
    // L6: GEMM2
    gemm_tc<<<gemm_blocks, 256>>>(feat1, 256, B2hi, B2lo, b2, out, M, 256);
    // L7: gather layer 2
    gather_kernel<<<gather_blocks, 256>>>(out + 128, out, row_start, edge_src, M);
}